// round 6
// baseline (speedup 1.0000x reference)
#include <cuda_runtime.h>
#include <cstdint>
#include <math.h>

// Problem constants: hidden_states (64, 577, 1024) fp32 -> out (64, 289, 1024) fp32
#define Bn   64
#define Tn   577
#define Cn   1024
#define NE   288   // even tokens that get merged (tokens 2,4,...,576); token 0 is always the single "unm"
#define NO   288   // odd tokens (merge destinations: 1,3,...,575)
#define TOUT 289

// Static device scratch (no runtime allocation allowed)
__device__ float g_rnormO[Bn * NO];        // 1/||x_odd|| per (b, j)
__device__ float g_pmax [Bn * NE * 3];     // per-(b,i) partial max over each of 3 j-tiles
__device__ int   g_pidx [Bn * NE * 3];     // matching argmax (global j)
__device__ int   g_dst  [Bn * NE];         // final dst(i)

// ---------- packed f32x2 helpers (FFMA2 path, sm_103a) ----------
__device__ __forceinline__ unsigned long long pack_dup(float a) {
    unsigned long long r; unsigned int u = __float_as_uint(a);
    asm("mov.b64 %0, {%1, %1};" : "=l"(r) : "r"(u));
    return r;
}
__device__ __forceinline__ void fma2(unsigned long long& acc, unsigned long long a, unsigned long long b) {
    asm("fma.rn.f32x2 %0, %1, %2, %0;" : "+l"(acc) : "l"(a), "l"(b));
}
__device__ __forceinline__ float2 unpack2(unsigned long long v) {
    unsigned int lo, hi;
    asm("mov.b64 {%0, %1}, %2;" : "=r"(lo), "=r"(hi) : "l"(v));
    return make_float2(__uint_as_float(lo), __uint_as_float(hi));
}

// ---------- K1: inverse norms of odd tokens (one warp per row) ----------
__global__ __launch_bounds__(256) void k_rnorm(const float* __restrict__ X) {
    int wid  = (blockIdx.x * blockDim.x + threadIdx.x) >> 5;
    int lane = threadIdx.x & 31;
    if (wid >= Bn * NO) return;
    int b = wid / NO, j = wid - b * NO;
    const float* p = X + ((size_t)b * Tn + (size_t)(2 * j + 1)) * Cn;
    float s = 0.f;
    #pragma unroll
    for (int i = 0; i < 8; i++) {
        float4 v = *(const float4*)(p + i * 128 + lane * 4);
        s += v.x * v.x + v.y * v.y + v.z * v.z + v.w * v.w;
    }
    #pragma unroll
    for (int o = 16; o > 0; o >>= 1) s += __shfl_xor_sync(0xffffffffu, s, o);
    if (lane == 0) g_rnormO[wid] = 1.0f / sqrtf(s);
}

// ---------- K2: fp32 GEMM (96x96 tile, K=1024) + per-row argmax over j-tile ----------
// Block = (b, it, jt). Each of 256 threads owns a 6x6 register tile (6 rows x 3 col-pairs, FFMA2).
// 288 = 3*96 on both axes -> no tails, no predication.
__global__ __launch_bounds__(256) void k_gemm_argmax(const float* __restrict__ X) {
    __shared__ __align__(16) float sA[32][98];   // [k][row], stride 98 keeps b64 loads 8B-aligned
    __shared__ __align__(16) float sB[32][98];   // [k][col], pre-scaled by rnorm_j

    const int b = blockIdx.z, it = blockIdx.y, jt = blockIdx.x;
    const int t = threadIdx.x;
    const int rg = t >> 4, cg = t & 15;          // 16 rowgroups x 16 colgroups
    const int q = t & 7,  r0 = t >> 3;           // global-load mapping: 8 float4 per 32-float row

    const float* Xb = X + (size_t)b * Tn * Cn;

    float rnB[3];
    #pragma unroll
    for (int ph = 0; ph < 3; ph++)
        rnB[ph] = g_rnormO[b * NO + jt * 96 + ph * 32 + r0];

    unsigned long long acc[6][3];
    #pragma unroll
    for (int u = 0; u < 6; u++)
        #pragma unroll
        for (int p = 0; p < 3; p++) acc[u][p] = 0ull;   // bits 0 == packed (+0.f, +0.f)

    for (int k0 = 0; k0 < Cn; k0 += 32) {
        __syncthreads();
        #pragma unroll
        for (int ph = 0; ph < 3; ph++) {
            const int r = ph * 32 + r0;
            // A row: even token 2*(i+1), i = it*96 + r  (i <= 287 -> token <= 576, in bounds)
            const float4 va = *(const float4*)(Xb + (size_t)(2 * (it * 96 + r + 1)) * Cn + k0 + q * 4);
            sA[q * 4 + 0][r] = va.x; sA[q * 4 + 1][r] = va.y;
            sA[q * 4 + 2][r] = va.z; sA[q * 4 + 3][r] = va.w;
            // B col: odd token 2*j+1, j = jt*96 + r; pre-scale by rnorm_j
            const float4 vb = *(const float4*)(Xb + (size_t)(2 * (jt * 96 + r) + 1) * Cn + k0 + q * 4);
            const float rn = rnB[ph];
            sB[q * 4 + 0][r] = vb.x * rn; sB[q * 4 + 1][r] = vb.y * rn;
            sB[q * 4 + 2][r] = vb.z * rn; sB[q * 4 + 3][r] = vb.w * rn;
        }
        __syncthreads();
        #pragma unroll
        for (int k = 0; k < 32; k++) {
            const unsigned long long bp0 = *(const unsigned long long*)&sB[k][cg * 6 + 0];
            const unsigned long long bp1 = *(const unsigned long long*)&sB[k][cg * 6 + 2];
            const unsigned long long bp2 = *(const unsigned long long*)&sB[k][cg * 6 + 4];
            #pragma unroll
            for (int u = 0; u < 6; u++) {
                const unsigned long long ad = pack_dup(sA[k][rg * 6 + u]);
                fma2(acc[u][0], ad, bp0);
                fma2(acc[u][1], ad, bp1);
                fma2(acc[u][2], ad, bp2);
            }
        }
    }

    // ---- epilogue: per-row argmax across this block's 96 columns ----
    __syncthreads();
    float* redM = &sA[0][0];        // 96 rows x 16 colgroups
    int*   redI = (int*)&sB[0][0];
    #pragma unroll
    for (int u = 0; u < 6; u++) {
        float m = -3.0e38f; int mi = 0;
        #pragma unroll
        for (int p = 0; p < 3; p++) {
            const float2 pr = unpack2(acc[u][p]);
            const int j0 = jt * 96 + cg * 6 + 2 * p;   // ascending j -> strict '>' keeps lowest on tie
            if (pr.x > m) { m = pr.x; mi = j0; }
            if (pr.y > m) { m = pr.y; mi = j0 + 1; }
        }
        const int row = rg * 6 + u;
        redM[row * 16 + cg] = m;
        redI[row * 16 + cg] = mi;
    }
    __syncthreads();
    if (t < 96) {
        float m = redM[t * 16]; int mi = redI[t * 16];
        #pragma unroll
        for (int c = 1; c < 16; c++) {                 // ascending cg == ascending j
            const float v = redM[t * 16 + c];
            if (v > m) { m = v; mi = redI[t * 16 + c]; }
        }
        const int i = it * 96 + t;
        g_pmax[(b * NE + i) * 3 + jt] = m;
        g_pidx[(b * NE + i) * 3 + jt] = mi;
    }
}

// ---------- K3: reduce 3 j-tile partials -> dst(i) ----------
__global__ void k_reduce_dst() {
    const int id = blockIdx.x * blockDim.x + threadIdx.x;
    if (id >= Bn * NE) return;
    float m = g_pmax[id * 3]; int mi = g_pidx[id * 3];
    float v1 = g_pmax[id * 3 + 1]; if (v1 > m) { m = v1; mi = g_pidx[id * 3 + 1]; }  // jt ascending = j ascending
    float v2 = g_pmax[id * 3 + 2]; if (v2 > m) { m = v2; mi = g_pidx[id * 3 + 2]; }
    g_dst[id] = mi;
}

// ---------- K4: merge (gather form, deterministic, no atomics) ----------
// One block per output row. Row 0 = copy of token 0. Row 1+j = mean of odd token 2j+1
// and all even tokens whose dst == j.
__global__ __launch_bounds__(256) void k_merge(const float* __restrict__ X, float* __restrict__ out) {
    __shared__ int s_d[NE];
    __shared__ int s_list[NE];
    __shared__ int s_cnt;
    const int b   = blockIdx.y;
    const int row = blockIdx.x;
    const int t   = threadIdx.x;
    float* orow = out + ((size_t)b * TOUT + row) * Cn;

    if (row == 0) {   // unm token (always original token 0, size 1 -> no division)
        const float4 v = *(const float4*)(X + (size_t)b * Tn * Cn + t * 4);
        *(float4*)(orow + t * 4) = v;
        return;
    }
    const int j = row - 1;
    for (int i = t; i < NE; i += 256) s_d[i] = g_dst[b * NE + i];
    __syncthreads();
    if (t == 0) {     // deterministic ascending-order source list
        int c = 0;
        for (int i = 0; i < NE; i++) if (s_d[i] == j) s_list[c++] = i;
        s_cnt = c;
    }
    __syncthreads();
    const int cnt = s_cnt;
    const float* Xb = X + (size_t)b * Tn * Cn;
    float4 a = *(const float4*)(Xb + (size_t)(2 * j + 1) * Cn + t * 4);
    for (int s = 0; s < cnt; s++) {
        const float4 v = *(const float4*)(Xb + (size_t)(2 * (s_list[s] + 1)) * Cn + t * 4);
        a.x += v.x; a.y += v.y; a.z += v.z; a.w += v.w;
    }
    const float inv = 1.0f / (float)(cnt + 1);
    a.x *= inv; a.y *= inv; a.z *= inv; a.w *= inv;
    *(float4*)(orow + t * 4) = a;
}

// ---------- launch ----------
extern "C" void kernel_launch(void* const* d_in, const int* in_sizes, int n_in,
                              void* d_out, int out_size) {
    const float* X = (const float*)d_in[0];
    float* out = (float*)d_out;

    k_rnorm      <<<(Bn * NO + 7) / 8, 256>>>(X);
    k_gemm_argmax<<<dim3(3, 3, Bn), 256>>>(X);
    k_reduce_dst <<<(Bn * NE + 255) / 256, 256>>>();
    k_merge      <<<dim3(TOUT, Bn), 256>>>(X, out);
}

// round 7
// speedup vs baseline: 1.7207x; 1.7207x over previous
#include <cuda_runtime.h>
#include <cstdint>
#include <math.h>

// Problem constants: hidden_states (64, 577, 1024) fp32 -> out (64, 289, 1024) fp32
#define Bn   64
#define Tn   577
#define Cn   1024
#define NE   288   // even tokens that get merged (tokens 2,4,...,576); token 0 is the single "unm"
#define NO   288   // odd tokens (merge destinations: 1,3,...,575)
#define TOUT 289

// Static device scratch (no runtime allocation allowed)
__device__ float g_rnormO[Bn * NO];        // 1/||x_odd|| per (b, j)
__device__ float g_pmax [Bn * NE * 3];     // per-(b,i) partial max over each of 3 j-tiles
__device__ int   g_pidx [Bn * NE * 3];     // matching argmax (global j)
__device__ int   g_off  [Bn * NO];         // CSR offsets per (b, j)
__device__ int   g_cnt  [Bn * NO];         // CSR counts per (b, j)
__device__ int   g_list [Bn * NE];         // CSR source lists (ascending i within each j)

// ---------- packed f32x2 helpers (FFMA2 path, sm_103a) ----------
__device__ __forceinline__ void fma2(unsigned long long& acc, unsigned long long a, unsigned long long b) {
    asm("fma.rn.f32x2 %0, %1, %2, %0;" : "+l"(acc) : "l"(a), "l"(b));
}
__device__ __forceinline__ float2 unpack2(unsigned long long v) {
    unsigned int lo, hi;
    asm("mov.b64 {%0, %1}, %2;" : "=r"(lo), "=r"(hi) : "l"(v));
    return make_float2(__uint_as_float(lo), __uint_as_float(hi));
}

// ---------- K1: inverse norms of odd tokens (one warp per row) ----------
__global__ __launch_bounds__(256) void k_rnorm(const float* __restrict__ X) {
    int wid  = (blockIdx.x * blockDim.x + threadIdx.x) >> 5;
    int lane = threadIdx.x & 31;
    if (wid >= Bn * NO) return;
    int b = wid / NO, j = wid - b * NO;
    const float* p = X + ((size_t)b * Tn + (size_t)(2 * j + 1)) * Cn;
    float s = 0.f;
    #pragma unroll
    for (int i = 0; i < 8; i++) {
        float4 v = *(const float4*)(p + i * 128 + lane * 4);
        s += v.x * v.x + v.y * v.y + v.z * v.z + v.w * v.w;
    }
    #pragma unroll
    for (int o = 16; o > 0; o >>= 1) s += __shfl_xor_sync(0xffffffffu, s, o);
    if (lane == 0) g_rnormO[wid] = 1.0f / sqrtf(s);
}

// ---------- K2: fp32 GEMM (96x96 tile, K=1024) + per-row argmax over j-tile ----------
// A is stored DUPLICATED in smem (each value at two adjacent floats) so the FFMA2
// broadcast operand {a,a} comes straight from one LDS.64 — no MOV dups in the
// inner loop. Global loads for the next k-tile are prefetched into registers
// before the current tile's compute, hiding LDG latency behind ~1150 fma cycles.
#define SA_STRIDE 194   // floats per k-row of sAd (192 used + pad; *4 bytes is 8B-aligned)
#define SB_STRIDE 98    // floats per k-row of sB
__global__ __launch_bounds__(256) void k_gemm_argmax(const float* __restrict__ X) {
    __shared__ __align__(16) float sAd[32][SA_STRIDE]; // [k][2*row {dup}]
    __shared__ __align__(16) float sB [32][SB_STRIDE]; // [k][col], pre-scaled by rnorm_j

    const int b = blockIdx.z, it = blockIdx.y, jt = blockIdx.x;
    const int t = threadIdx.x;
    const int rg = t >> 4, cg = t & 15;          // 16 rowgroups x 16 colgroups (6x6 regs each)
    const int q = t & 7,  r0 = t >> 3;           // global-load mapping: 8 float4 per 32-float row

    const float* Xb = X + (size_t)b * Tn * Cn;

    // Per-phase base pointers (ph = which 32-row slab of the 96 this thread loads)
    const float* pA[3]; const float* pB[3]; float rnB[3];
    #pragma unroll
    for (int ph = 0; ph < 3; ph++) {
        const int r = ph * 32 + r0;
        pA[ph] = Xb + (size_t)(2 * (it * 96 + r + 1)) * Cn + q * 4;     // even token row
        pB[ph] = Xb + (size_t)(2 * (jt * 96 + r) + 1) * Cn + q * 4;     // odd token row
        rnB[ph] = g_rnormO[b * NO + jt * 96 + r];
    }

    unsigned long long acc[6][3];
    #pragma unroll
    for (int u = 0; u < 6; u++)
        #pragma unroll
        for (int p = 0; p < 3; p++) acc[u][p] = 0ull;   // bits 0 == packed (+0.f, +0.f)

    // Prefetch tile 0
    float4 va[3], vb[3];
    #pragma unroll
    for (int ph = 0; ph < 3; ph++) { va[ph] = *(const float4*)(pA[ph]); vb[ph] = *(const float4*)(pB[ph]); }

    #pragma unroll 1
    for (int kt = 0; kt < 32; kt++) {
        // ---- store prefetched regs to smem ----
        #pragma unroll
        for (int ph = 0; ph < 3; ph++) {
            const int r = ph * 32 + r0;
            const float rn = rnB[ph];
            *(float2*)&sAd[q * 4 + 0][2 * r] = make_float2(va[ph].x, va[ph].x);
            *(float2*)&sAd[q * 4 + 1][2 * r] = make_float2(va[ph].y, va[ph].y);
            *(float2*)&sAd[q * 4 + 2][2 * r] = make_float2(va[ph].z, va[ph].z);
            *(float2*)&sAd[q * 4 + 3][2 * r] = make_float2(va[ph].w, va[ph].w);
            sB[q * 4 + 0][r] = vb[ph].x * rn;
            sB[q * 4 + 1][r] = vb[ph].y * rn;
            sB[q * 4 + 2][r] = vb[ph].z * rn;
            sB[q * 4 + 3][r] = vb[ph].w * rn;
        }
        __syncthreads();
        // ---- issue next tile's global loads (latency hidden by compute) ----
        if (kt < 31) {
            const int k0 = (kt + 1) * 32;
            #pragma unroll
            for (int ph = 0; ph < 3; ph++) {
                va[ph] = *(const float4*)(pA[ph] + k0);
                vb[ph] = *(const float4*)(pB[ph] + k0);
            }
        }
        // ---- compute: 32 k-steps, 18 FFMA2 + 9 LDS.64 per step ----
        #pragma unroll
        for (int k = 0; k < 32; k++) {
            const unsigned long long bp0 = *(const unsigned long long*)&sB[k][cg * 6 + 0];
            const unsigned long long bp1 = *(const unsigned long long*)&sB[k][cg * 6 + 2];
            const unsigned long long bp2 = *(const unsigned long long*)&sB[k][cg * 6 + 4];
            #pragma unroll
            for (int u = 0; u < 6; u++) {
                const unsigned long long ad = *(const unsigned long long*)&sAd[k][(rg * 6 + u) * 2];
                fma2(acc[u][0], ad, bp0);
                fma2(acc[u][1], ad, bp1);
                fma2(acc[u][2], ad, bp2);
            }
        }
        __syncthreads();   // protect smem before next tile's stores / epilogue reuse
    }

    // ---- epilogue: per-row argmax across this block's 96 columns ----
    float* redM = &sAd[0][0];        // 96 rows x 16 colgroups
    int*   redI = (int*)&sB[0][0];
    #pragma unroll
    for (int u = 0; u < 6; u++) {
        float m = -3.0e38f; int mi = 0;
        #pragma unroll
        for (int p = 0; p < 3; p++) {
            const float2 pr = unpack2(acc[u][p]);
            const int j0 = jt * 96 + cg * 6 + 2 * p;   // ascending j -> strict '>' keeps lowest on tie
            if (pr.x > m) { m = pr.x; mi = j0; }
            if (pr.y > m) { m = pr.y; mi = j0 + 1; }
        }
        const int row = rg * 6 + u;
        redM[row * 16 + cg] = m;
        redI[row * 16 + cg] = mi;
    }
    __syncthreads();
    if (t < 96) {
        float m = redM[t * 16]; int mi = redI[t * 16];
        #pragma unroll
        for (int c = 1; c < 16; c++) {                 // ascending cg == ascending j
            const float v = redM[t * 16 + c];
            if (v > m) { m = v; mi = redI[t * 16 + c]; }
        }
        const int i = it * 96 + t;
        g_pmax[(b * NE + i) * 3 + jt] = m;
        g_pidx[(b * NE + i) * 3 + jt] = mi;
    }
}

// ---------- K3: reduce j-tile partials -> dst, then build deterministic CSR ----------
// One block per batch, 288 threads. No atomics: thread j scans dst[] to count and
// emit its ascending source list. Bitwise deterministic across runs.
__global__ __launch_bounds__(288) void k_build_csr() {
    __shared__ int s_dst[NE];
    __shared__ int s_cnt[NO];
    __shared__ int s_off[NO];
    const int b = blockIdx.x, t = threadIdx.x;     // t in [0, 288)

    // reduce the 3 j-tile partials for row i = t
    const int id = b * NE + t;
    float m = g_pmax[id * 3]; int mi = g_pidx[id * 3];
    float v1 = g_pmax[id * 3 + 1]; if (v1 > m) { m = v1; mi = g_pidx[id * 3 + 1]; }
    float v2 = g_pmax[id * 3 + 2]; if (v2 > m) { m = v2; mi = g_pidx[id * 3 + 2]; }
    s_dst[t] = mi;
    __syncthreads();

    // count sources targeting j = t
    int c = 0;
    for (int i = 0; i < NE; i++) c += (s_dst[i] == t);
    s_cnt[t] = c;
    __syncthreads();

    if (t == 0) {  // serial exclusive prefix sum over 288 counts (cheap, 64 blocks in parallel)
        int acc = 0;
        for (int j = 0; j < NO; j++) { s_off[j] = acc; acc += s_cnt[j]; }
    }
    __syncthreads();

    const int off = s_off[t];
    int w = 0;
    for (int i = 0; i < NE; i++)
        if (s_dst[i] == t) g_list[b * NE + off + (w++)] = i;
    g_off[b * NO + t] = off;
    g_cnt[b * NO + t] = c;
}

// ---------- K4: merge via CSR gather (deterministic, no per-block serial scan) ----------
__global__ __launch_bounds__(256) void k_merge(const float* __restrict__ X, float* __restrict__ out) {
    const int b   = blockIdx.y;
    const int row = blockIdx.x;
    const int t   = threadIdx.x;
    float* orow = out + ((size_t)b * TOUT + row) * Cn;
    const float* Xb = X + (size_t)b * Tn * Cn;

    if (row == 0) {   // unm token (always original token 0, size 1 -> plain copy)
        *(float4*)(orow + t * 4) = *(const float4*)(Xb + t * 4);
        return;
    }
    const int j   = row - 1;
    const int off = g_off[b * NO + j];
    const int cnt = g_cnt[b * NO + j];

    float4 a = *(const float4*)(Xb + (size_t)(2 * j + 1) * Cn + t * 4);
    for (int s = 0; s < cnt; s++) {
        const int i = g_list[b * NE + off + s];       // ascending i -> fixed fp order
        const float4 v = *(const float4*)(Xb + (size_t)(2 * (i + 1)) * Cn + t * 4);
        a.x += v.x; a.y += v.y; a.z += v.z; a.w += v.w;
    }
    const float inv = 1.0f / (float)(cnt + 1);
    a.x *= inv; a.y *= inv; a.z *= inv; a.w *= inv;
    *(float4*)(orow + t * 4) = a;
}

// ---------- launch ----------
extern "C" void kernel_launch(void* const* d_in, const int* in_sizes, int n_in,
                              void* d_out, int out_size) {
    const float* X = (const float*)d_in[0];
    float* out = (float*)d_out;

    k_rnorm      <<<(Bn * NO + 7) / 8, 256>>>(X);
    k_gemm_argmax<<<dim3(3, 3, Bn), 256>>>(X);
    k_build_csr  <<<Bn, 288>>>();
    k_merge      <<<dim3(TOUT, Bn), 256>>>(X, out);
}

// round 9
// speedup vs baseline: 3.5253x; 2.0487x over previous
#include <cuda_runtime.h>
#include <cuda_bf16.h>
#include <cstdint>
#include <math.h>

// Problem: hidden_states (64, 577, 1024) fp32 -> out (64, 289, 1024) fp32
#define Bn   64
#define Tn   577
#define Cn   1024
#define NE   288      // even tokens (2,4,...,576) that merge into odds
#define NO   288      // odd tokens (1,3,...,575) = merge destinations
#define TOUT 289

// ---- static device scratch (no runtime allocation allowed) ----
__device__ __nv_bfloat16 g_Abf[Bn * NE * Cn];     // bf16(a_i)
__device__ __nv_bfloat16 g_Bbf[Bn * NO * Cn];     // bf16(b_j * rnorm_j)
__device__ float g_anorm [Bn * NE];
__device__ float g_rnormO[Bn * NO];
__device__ float g_scores[(size_t)Bn * NE * NO];  // approx scores, row-major [b][i][j]
__device__ int   g_dst   [Bn * NE];
__device__ int   g_off   [Bn * NO];
__device__ int   g_cnt   [Bn * NO];
__device__ int   g_list  [Bn * NE];

// ---------------- helpers ----------------
__device__ __forceinline__ uint32_t smem_u32(const void* p) {
    uint32_t a;
    asm("{ .reg .u64 t; cvta.to.shared.u64 t, %1; cvt.u32.u64 %0, t; }" : "=r"(a) : "l"(p));
    return a;
}
__device__ __forceinline__ void ldm_x4(uint32_t* r, uint32_t addr) {
    asm volatile("ldmatrix.sync.aligned.m8n8.x4.shared.b16 {%0,%1,%2,%3}, [%4];"
        : "=r"(r[0]), "=r"(r[1]), "=r"(r[2]), "=r"(r[3]) : "r"(addr));
}
__device__ __forceinline__ void ldm_x2(uint32_t* r, uint32_t addr) {
    asm volatile("ldmatrix.sync.aligned.m8n8.x2.shared.b16 {%0,%1}, [%2];"
        : "=r"(r[0]), "=r"(r[1]) : "r"(addr));
}
__device__ __forceinline__ void mma_bf16(float* c, const uint32_t* a, const uint32_t* bfr) {
    asm volatile("mma.sync.aligned.m16n8k16.row.col.f32.bf16.bf16.f32 "
        "{%0,%1,%2,%3}, {%4,%5,%6,%7}, {%8,%9}, {%0,%1,%2,%3};"
        : "+f"(c[0]), "+f"(c[1]), "+f"(c[2]), "+f"(c[3])
        : "r"(a[0]), "r"(a[1]), "r"(a[2]), "r"(a[3]), "r"(bfr[0]), "r"(bfr[1]));
}

// ---------------- K0: prep — norms + bf16 operand conversion ----------------
__global__ __launch_bounds__(128) void k_prep(const float* __restrict__ X) {
    __shared__ float red[4];
    const int token = blockIdx.x + 1;       // skip token 0 (the lone "unm")
    const int b = blockIdx.y, t = threadIdx.x, lane = t & 31, w = t >> 5;
    const float* p = X + ((size_t)b * Tn + token) * Cn;
    const float4 v0 = *(const float4*)(p + t * 8);
    const float4 v1 = *(const float4*)(p + t * 8 + 4);
    float ss = v0.x*v0.x + v0.y*v0.y + v0.z*v0.z + v0.w*v0.w
             + v1.x*v1.x + v1.y*v1.y + v1.z*v1.z + v1.w*v1.w;
    #pragma unroll
    for (int o = 16; o > 0; o >>= 1) ss += __shfl_xor_sync(0xffffffffu, ss, o);
    if (lane == 0) red[w] = ss;
    __syncthreads();
    const float sum = red[0] + red[1] + red[2] + red[3];   // deterministic order

    if (token & 1) {
        const int j = (token - 1) >> 1;
        const float rn = 1.0f / sqrtf(sum);
        if (t == 0) g_rnormO[b * NO + j] = rn;
        __nv_bfloat162* d = (__nv_bfloat162*)(g_Bbf + ((size_t)b * NO + j) * Cn) + t * 4;
        d[0] = __floats2bfloat162_rn(v0.x * rn, v0.y * rn);
        d[1] = __floats2bfloat162_rn(v0.z * rn, v0.w * rn);
        d[2] = __floats2bfloat162_rn(v1.x * rn, v1.y * rn);
        d[3] = __floats2bfloat162_rn(v1.z * rn, v1.w * rn);
    } else {
        const int i = token / 2 - 1;
        if (t == 0) g_anorm[b * NE + i] = sqrtf(sum);
        __nv_bfloat162* d = (__nv_bfloat162*)(g_Abf + ((size_t)b * NE + i) * Cn) + t * 4;
        d[0] = __floats2bfloat162_rn(v0.x, v0.y);
        d[1] = __floats2bfloat162_rn(v0.z, v0.w);
        d[2] = __floats2bfloat162_rn(v1.x, v1.y);
        d[3] = __floats2bfloat162_rn(v1.z, v1.w);
    }
}

// ---------------- K1: bf16 mma.sync GEMM -> approx scores ----------------
// Block (jt, it, b): D[96 x 96] = A[96 x 1024] @ B[96 x 1024]^T, fp32 accum.
// 8 warps in 2(M) x 4(N); each warp: 48x24 = 3x3 m16n8k16 tiles, 36 accum regs.
// K streamed in 16 chunks of 64; smem row stride 72 bf16 (144 B) -> every
// ldmatrix phase (8 rows x 16B) covers all 32 banks conflict-free.
#define KC   64
#define LDS_STRIDE 72
__global__ __launch_bounds__(256) void k_gemm() {
    __shared__ __align__(16) __nv_bfloat16 sA[96 * LDS_STRIDE];
    __shared__ __align__(16) __nv_bfloat16 sB[96 * LDS_STRIDE];

    const int b = blockIdx.z, it = blockIdx.y, jt = blockIdx.x;
    const int tid = threadIdx.x, wid = tid >> 5, lane = tid & 31;
    const int wm = wid >> 2, wn = wid & 3;           // warp grid 2 x 4

    const __nv_bfloat16* Ag = g_Abf + ((size_t)b * NE + it * 96) * Cn;
    const __nv_bfloat16* Bg = g_Bbf + ((size_t)b * NO + jt * 96) * Cn;

    // Global-load mapping: 96 rows x 8 uint4 per chunk = 768 uint4 = 3 x 256
    int rowL[3], segL[3];
    #pragma unroll
    for (int u = 0; u < 3; u++) { const int v = tid + u * 256; rowL[u] = v >> 3; segL[u] = v & 7; }

    const uint32_t aBase = smem_u32(sA);
    const uint32_t bBase = smem_u32(sB);

    // ldmatrix source addresses (byte units; bf16 *2)
    uint32_t aAddr[3], bAddr[3];
    #pragma unroll
    for (int s = 0; s < 3; s++)
        aAddr[s] = aBase + (((wm * 48 + s * 16 + (lane & 15)) * LDS_STRIDE + (lane >> 4) * 8) << 1);
    #pragma unroll
    for (int p = 0; p < 3; p++)
        bAddr[p] = bBase + (((wn * 24 + p * 8 + (lane & 7)) * LDS_STRIDE + ((lane >> 3) & 1) * 8) << 1);

    float acc[3][3][4];
    #pragma unroll
    for (int s = 0; s < 3; s++)
        #pragma unroll
        for (int p = 0; p < 3; p++)
            #pragma unroll
            for (int e = 0; e < 4; e++) acc[s][p][e] = 0.f;

    // prefetch chunk 0
    uint4 pa[3], pb[3];
    #pragma unroll
    for (int u = 0; u < 3; u++) {
        pa[u] = *(const uint4*)(Ag + (size_t)rowL[u] * Cn + segL[u] * 8);
        pb[u] = *(const uint4*)(Bg + (size_t)rowL[u] * Cn + segL[u] * 8);
    }

    #pragma unroll 1
    for (int kt = 0; kt < Cn / KC; kt++) {
        __syncthreads();                         // previous compute done reading smem
        #pragma unroll
        for (int u = 0; u < 3; u++) {
            *(uint4*)(sA + rowL[u] * LDS_STRIDE + segL[u] * 8) = pa[u];
            *(uint4*)(sB + rowL[u] * LDS_STRIDE + segL[u] * 8) = pb[u];
        }
        __syncthreads();
        if (kt < Cn / KC - 1) {                  // prefetch next chunk (latency hidden)
            const int k0 = (kt + 1) * KC;
            #pragma unroll
            for (int u = 0; u < 3; u++) {
                pa[u] = *(const uint4*)(Ag + (size_t)rowL[u] * Cn + k0 + segL[u] * 8);
                pb[u] = *(const uint4*)(Bg + (size_t)rowL[u] * Cn + k0 + segL[u] * 8);
            }
        }
        #pragma unroll
        for (int step = 0; step < KC / 16; step++) {
            uint32_t aF[3][4], bF[3][2];
            #pragma unroll
            for (int s = 0; s < 3; s++) ldm_x4(aF[s], aAddr[s] + (step * 16 << 1));
            #pragma unroll
            for (int p = 0; p < 3; p++) ldm_x2(bF[p], bAddr[p] + (step * 16 << 1));
            #pragma unroll
            for (int s = 0; s < 3; s++)
                #pragma unroll
                for (int p = 0; p < 3; p++) mma_bf16(acc[s][p], aF[s], bF[p]);
        }
    }

    // epilogue: write scores (row-major [b][i][j])
    float* sc = g_scores + ((size_t)b * NE + it * 96) * NO + jt * 96;
    const int tr = lane >> 2, tc = (lane & 3) * 2;
    #pragma unroll
    for (int s = 0; s < 3; s++) {
        #pragma unroll
        for (int p = 0; p < 3; p++) {
            const int r0 = wm * 48 + s * 16 + tr;
            const int c  = wn * 24 + p * 8 + tc;
            *(float2*)(sc + (size_t)r0 * NO + c)       = make_float2(acc[s][p][0], acc[s][p][1]);
            *(float2*)(sc + (size_t)(r0 + 8) * NO + c) = make_float2(acc[s][p][2], acc[s][p][3]);
        }
    }
}

// ---------------- K2: fused candidate filter + exact fp32 re-verify ----------------
// One warp per (b, i): scan 288 approx scores, window [max - 2B, max] with
// B = 0.006*|a_i| (rigorous bound 0.0041*|a_i|), re-verify candidates exactly.
__device__ __forceinline__ float exact_score(const float4 a[8], const float* __restrict__ pb,
                                             int lane, float rn) {
    float s = 0.f;
    #pragma unroll
    for (int q = 0; q < 8; q++) {
        const float4 v = *(const float4*)(pb + q * 128 + lane * 4);
        s += a[q].x * v.x + a[q].y * v.y + a[q].z * v.z + a[q].w * v.w;
    }
    #pragma unroll
    for (int o = 16; o > 0; o >>= 1) s += __shfl_xor_sync(0xffffffffu, s, o);
    return s * rn;
}

__global__ __launch_bounds__(256) void k_filter_exact(const float* __restrict__ X) {
    const int w = threadIdx.x >> 5, lane = threadIdx.x & 31;
    const int b = blockIdx.x / 36, sub = blockIdx.x % 36;   // group by b -> L2 reuse of odd rows
    const int i = sub * 8 + w;
    const float* Xb = X + (size_t)b * Tn * Cn;

    // load my 9 scores (j = q*32 + lane)
    const float* srow = g_scores + ((size_t)b * NE + i) * NO;
    float sc[9];
    #pragma unroll
    for (int q = 0; q < 9; q++) sc[q] = srow[q * 32 + lane];

    float m = sc[0];
    #pragma unroll
    for (int q = 1; q < 9; q++) m = fmaxf(m, sc[q]);
    #pragma unroll
    for (int o = 16; o > 0; o >>= 1) m = fmaxf(m, __shfl_xor_sync(0xffffffffu, m, o));
    const float thr = m - 0.012f * g_anorm[b * NE + i];

    // cache a_i in registers
    float4 a[8];
    const float* pa = Xb + (size_t)(2 * i + 2) * Cn;
    #pragma unroll
    for (int q = 0; q < 8; q++) a[q] = *(const float4*)(pa + q * 128 + lane * 4);

    float best = -3.0e38f; int bj = 0;
    #pragma unroll 1
    for (int q = 0; q < 9; q++) {                 // ascending q, ascending bit => ascending j
        unsigned mask = __ballot_sync(0xffffffffu, sc[q] >= thr);
        while (mask) {
            const int bit = __ffs(mask) - 1;
            mask &= mask - 1;
            const int j = q * 32 + bit;
            const float v = exact_score(a, Xb + (size_t)(2 * j + 1) * Cn, lane, g_rnormO[b * NO + j]);
            if (v > best) { best = v; bj = j; }   // strict '>' keeps lowest j on tie
        }
    }
    if (lane == 0) g_dst[b * NE + i] = bj;
}

// ---------------- K3: deterministic CSR build (no atomics) ----------------
__global__ __launch_bounds__(288) void k_build_csr() {
    __shared__ int s_dst[NE];
    __shared__ int s_cnt[NO];
    __shared__ int s_off[NO];
    const int b = blockIdx.x, t = threadIdx.x;
    s_dst[t] = g_dst[b * NE + t];
    __syncthreads();
    int c = 0;
    for (int i = 0; i < NE; i++) c += (s_dst[i] == t);
    s_cnt[t] = c;
    __syncthreads();
    if (t == 0) {
        int acc = 0;
        for (int j = 0; j < NO; j++) { s_off[j] = acc; acc += s_cnt[j]; }
    }
    __syncthreads();
    const int off = s_off[t];
    int wv = 0;
    for (int i = 0; i < NE; i++)
        if (s_dst[i] == t) g_list[b * NE + off + (wv++)] = i;
    g_off[b * NO + t] = off;
    g_cnt[b * NO + t] = c;
}

// ---------------- K4: merge via CSR gather ----------------
__global__ __launch_bounds__(256) void k_merge(const float* __restrict__ X, float* __restrict__ out) {
    const int b = blockIdx.y, row = blockIdx.x, t = threadIdx.x;
    float* orow = out + ((size_t)b * TOUT + row) * Cn;
    const float* Xb = X + (size_t)b * Tn * Cn;

    if (row == 0) {   // lone unm token = original token 0
        *(float4*)(orow + t * 4) = *(const float4*)(Xb + t * 4);
        return;
    }
    const int j = row - 1;
    const int off = g_off[b * NO + j];
    const int cnt = g_cnt[b * NO + j];
    float4 a = *(const float4*)(Xb + (size_t)(2 * j + 1) * Cn + t * 4);
    for (int s = 0; s < cnt; s++) {
        const int i = g_list[b * NE + off + s];               // ascending i -> fixed fp order
        const float4 v = *(const float4*)(Xb + (size_t)(2 * (i + 1)) * Cn + t * 4);
        a.x += v.x; a.y += v.y; a.z += v.z; a.w += v.w;
    }
    const float inv = 1.0f / (float)(cnt + 1);
    a.x *= inv; a.y *= inv; a.z *= inv; a.w *= inv;
    *(float4*)(orow + t * 4) = a;
}

// ---------------- launch ----------------
extern "C" void kernel_launch(void* const* d_in, const int* in_sizes, int n_in,
                              void* d_out, int out_size) {
    const float* X = (const float*)d_in[0];
    float* out = (float*)d_out;

    k_prep        <<<dim3(Tn - 1, Bn), 128>>>(X);
    k_gemm        <<<dim3(3, 3, Bn), 256>>>();
    k_filter_exact<<<Bn * 36, 256>>>(X);
    k_build_csr   <<<Bn, 288>>>();
    k_merge       <<<dim3(TOUT, Bn), 256>>>(X, out);
}

// round 10
// speedup vs baseline: 4.0058x; 1.1363x over previous
#include <cuda_runtime.h>
#include <cuda_bf16.h>
#include <cstdint>
#include <math.h>

// Problem: hidden_states (64, 577, 1024) fp32 -> out (64, 289, 1024) fp32
#define Bn   64
#define Tn   577
#define Cn   1024
#define NE   288      // even tokens (2,4,...,576) that merge into odds
#define NO   288      // odd tokens (1,3,...,575) = merge destinations
#define TOUT 289

// ---- static device scratch (no runtime allocation allowed) ----
__device__ float g_anorm [Bn * NE];
__device__ float g_rnormO[Bn * NO];
__device__ float g_scores[(size_t)Bn * NE * NO];  // raw bf16-dot scores [b][i][j]
__device__ int   g_dst   [Bn * NE];
__device__ int   g_off   [Bn * NO];
__device__ int   g_cnt   [Bn * NO];
__device__ int   g_list  [Bn * NE];

// ---------------- helpers ----------------
__device__ __forceinline__ uint32_t smem_u32(const void* p) {
    uint32_t a;
    asm("{ .reg .u64 t; cvta.to.shared.u64 t, %1; cvt.u32.u64 %0, t; }" : "=r"(a) : "l"(p));
    return a;
}
__device__ __forceinline__ void ldm_x4(uint32_t* r, uint32_t addr) {
    asm volatile("ldmatrix.sync.aligned.m8n8.x4.shared.b16 {%0,%1,%2,%3}, [%4];"
        : "=r"(r[0]), "=r"(r[1]), "=r"(r[2]), "=r"(r[3]) : "r"(addr));
}
__device__ __forceinline__ void ldm_x2(uint32_t* r, uint32_t addr) {
    asm volatile("ldmatrix.sync.aligned.m8n8.x2.shared.b16 {%0,%1}, [%2];"
        : "=r"(r[0]), "=r"(r[1]) : "r"(addr));
}
__device__ __forceinline__ void mma_bf16(float* c, const uint32_t* a, const uint32_t* bfr) {
    asm volatile("mma.sync.aligned.m16n8k16.row.col.f32.bf16.bf16.f32 "
        "{%0,%1,%2,%3}, {%4,%5,%6,%7}, {%8,%9}, {%0,%1,%2,%3};"
        : "+f"(c[0]), "+f"(c[1]), "+f"(c[2]), "+f"(c[3])
        : "r"(a[0]), "r"(a[1]), "r"(a[2]), "r"(a[3]), "r"(bfr[0]), "r"(bfr[1]));
}
__device__ __forceinline__ uint32_t pk(float x, float y) {
    __nv_bfloat162 h = __floats2bfloat162_rn(x, y);
    return *(uint32_t*)&h;
}

// ---------------- K1: fused fp32->bf16 GEMM + norms -> raw approx scores ----------------
// Block (jt, it, b): D[96 x 96] = bf16(A[96 x 1024]) @ bf16(B[96 x 1024])^T, fp32 accum.
// Loads fp32 X directly (L2-cached across the 9 blocks per batch), converts in
// registers, and accumulates sum-of-squares for norms on the edge blocks
// (jt==0 -> anorm of even rows; it==0 -> rnorm of odd rows), in a fixed
// deterministic order (per-thread segments + 8-lane shfl tree).
#define KC   64
#define LDS_STRIDE 72
__global__ __launch_bounds__(256) void k_gemm(const float* __restrict__ X) {
    __shared__ __align__(16) __nv_bfloat16 sA[96 * LDS_STRIDE];
    __shared__ __align__(16) __nv_bfloat16 sB[96 * LDS_STRIDE];

    const int b = blockIdx.z, it = blockIdx.y, jt = blockIdx.x;
    const int tid = threadIdx.x, wid = tid >> 5, lane = tid & 31;
    const int wm = wid >> 2, wn = wid & 3;           // warp grid 2 x 4

    // Global-load mapping: 96 rows x 8 segments of 8 floats; 768 jobs = 3 x 256
    int rowL[3], segL[3];
    #pragma unroll
    for (int u = 0; u < 3; u++) { const int v = tid + u * 256; rowL[u] = v >> 3; segL[u] = v & 7; }

    const float* Arow[3]; const float* Brow[3];
    #pragma unroll
    for (int u = 0; u < 3; u++) {
        Arow[u] = X + ((size_t)b * Tn + 2 * (it * 96 + rowL[u] + 1)) * Cn + segL[u] * 8;  // even token
        Brow[u] = X + ((size_t)b * Tn + 2 * (jt * 96 + rowL[u]) + 1) * Cn + segL[u] * 8;  // odd token
    }

    const uint32_t aBase = smem_u32(sA);
    const uint32_t bBase = smem_u32(sB);
    uint32_t aAddr[3], bAddr[3];
    #pragma unroll
    for (int s = 0; s < 3; s++)
        aAddr[s] = aBase + (((wm * 48 + s * 16 + (lane & 15)) * LDS_STRIDE + (lane >> 4) * 8) << 1);
    #pragma unroll
    for (int p = 0; p < 3; p++)
        bAddr[p] = bBase + (((wn * 24 + p * 8 + (lane & 7)) * LDS_STRIDE + ((lane >> 3) & 1) * 8) << 1);

    float acc[3][3][4];
    #pragma unroll
    for (int s = 0; s < 3; s++)
        #pragma unroll
        for (int p = 0; p < 3; p++)
            #pragma unroll
            for (int e = 0; e < 4; e++) acc[s][p][e] = 0.f;

    float sqa[3] = {0.f, 0.f, 0.f}, sqb[3] = {0.f, 0.f, 0.f};

    // prefetch chunk 0 (fp32: 2 float4 per matrix per job)
    float4 pa0[3], pa1[3], pb0[3], pb1[3];
    #pragma unroll
    for (int u = 0; u < 3; u++) {
        pa0[u] = *(const float4*)(Arow[u]);     pa1[u] = *(const float4*)(Arow[u] + 4);
        pb0[u] = *(const float4*)(Brow[u]);     pb1[u] = *(const float4*)(Brow[u] + 4);
    }

    #pragma unroll 1
    for (int kt = 0; kt < Cn / KC; kt++) {
        __syncthreads();                         // previous compute done reading smem
        #pragma unroll
        for (int u = 0; u < 3; u++) {
            uint4 va, vb;
            va.x = pk(pa0[u].x, pa0[u].y); va.y = pk(pa0[u].z, pa0[u].w);
            va.z = pk(pa1[u].x, pa1[u].y); va.w = pk(pa1[u].z, pa1[u].w);
            vb.x = pk(pb0[u].x, pb0[u].y); vb.y = pk(pb0[u].z, pb0[u].w);
            vb.z = pk(pb1[u].x, pb1[u].y); vb.w = pk(pb1[u].z, pb1[u].w);
            *(uint4*)(sA + rowL[u] * LDS_STRIDE + segL[u] * 8) = va;
            *(uint4*)(sB + rowL[u] * LDS_STRIDE + segL[u] * 8) = vb;
        }
        if (jt == 0) {   // uniform branch: accumulate even-row sum of squares
            #pragma unroll
            for (int u = 0; u < 3; u++)
                sqa[u] += pa0[u].x*pa0[u].x + pa0[u].y*pa0[u].y + pa0[u].z*pa0[u].z + pa0[u].w*pa0[u].w
                        + pa1[u].x*pa1[u].x + pa1[u].y*pa1[u].y + pa1[u].z*pa1[u].z + pa1[u].w*pa1[u].w;
        }
        if (it == 0) {   // uniform branch: accumulate odd-row sum of squares
            #pragma unroll
            for (int u = 0; u < 3; u++)
                sqb[u] += pb0[u].x*pb0[u].x + pb0[u].y*pb0[u].y + pb0[u].z*pb0[u].z + pb0[u].w*pb0[u].w
                        + pb1[u].x*pb1[u].x + pb1[u].y*pb1[u].y + pb1[u].z*pb1[u].z + pb1[u].w*pb1[u].w;
        }
        __syncthreads();
        if (kt < Cn / KC - 1) {                  // prefetch next chunk (latency hidden)
            const int k0 = (kt + 1) * KC;
            #pragma unroll
            for (int u = 0; u < 3; u++) {
                pa0[u] = *(const float4*)(Arow[u] + k0);     pa1[u] = *(const float4*)(Arow[u] + k0 + 4);
                pb0[u] = *(const float4*)(Brow[u] + k0);     pb1[u] = *(const float4*)(Brow[u] + k0 + 4);
            }
        }
        #pragma unroll
        for (int step = 0; step < KC / 16; step++) {
            uint32_t aF[3][4], bF[3][2];
            #pragma unroll
            for (int s = 0; s < 3; s++) ldm_x4(aF[s], aAddr[s] + (step * 16 << 1));
            #pragma unroll
            for (int p = 0; p < 3; p++) ldm_x2(bF[p], bAddr[p] + (step * 16 << 1));
            #pragma unroll
            for (int s = 0; s < 3; s++)
                #pragma unroll
                for (int p = 0; p < 3; p++) mma_bf16(acc[s][p], aF[s], bF[p]);
        }
    }

    // ---- norms: 8-lane tree (lanes sharing a row are contiguous lane>>3 groups) ----
    if (jt == 0) {
        #pragma unroll
        for (int u = 0; u < 3; u++) {
            float s = sqa[u];
            #pragma unroll
            for (int o = 1; o < 8; o <<= 1) s += __shfl_xor_sync(0xffffffffu, s, o);
            if ((lane & 7) == 0) g_anorm[b * NE + it * 96 + rowL[u]] = sqrtf(s);
        }
    }
    if (it == 0) {
        #pragma unroll
        for (int u = 0; u < 3; u++) {
            float s = sqb[u];
            #pragma unroll
            for (int o = 1; o < 8; o <<= 1) s += __shfl_xor_sync(0xffffffffu, s, o);
            if ((lane & 7) == 0) g_rnormO[b * NO + jt * 96 + rowL[u]] = 1.0f / sqrtf(s);
        }
    }

    // ---- epilogue: write raw scores (row-major [b][i][j]) ----
    float* sc = g_scores + ((size_t)b * NE + it * 96) * NO + jt * 96;
    const int tr = lane >> 2, tc = (lane & 3) * 2;
    #pragma unroll
    for (int s = 0; s < 3; s++) {
        #pragma unroll
        for (int p = 0; p < 3; p++) {
            const int r0 = wm * 48 + s * 16 + tr;
            const int c  = wn * 24 + p * 8 + tc;
            *(float2*)(sc + (size_t)r0 * NO + c)       = make_float2(acc[s][p][0], acc[s][p][1]);
            *(float2*)(sc + (size_t)(r0 + 8) * NO + c) = make_float2(acc[s][p][2], acc[s][p][3]);
        }
    }
}

// ---------------- K2: fused candidate filter + exact fp32 re-verify ----------------
// One warp per (b, i): normalize 288 raw scores by rn_j (fp32), window
// [max - 2B, max] with B = 0.006*|a_i| (rigorous bound 0.0041*|a_i|),
// re-verify candidates exactly in fp32 (ascending j, strict '>' tie-break).
__device__ __forceinline__ float exact_score(const float4 a[8], const float* __restrict__ pb,
                                             int lane, float rn) {
    float s = 0.f;
    #pragma unroll
    for (int q = 0; q < 8; q++) {
        const float4 v = *(const float4*)(pb + q * 128 + lane * 4);
        s += a[q].x * v.x + a[q].y * v.y + a[q].z * v.z + a[q].w * v.w;
    }
    #pragma unroll
    for (int o = 16; o > 0; o >>= 1) s += __shfl_xor_sync(0xffffffffu, s, o);
    return s * rn;
}

__global__ __launch_bounds__(256) void k_filter_exact(const float* __restrict__ X) {
    const int w = threadIdx.x >> 5, lane = threadIdx.x & 31;
    const int b = blockIdx.x / 36, sub = blockIdx.x % 36;   // group by b -> L2 reuse of odd rows
    const int i = sub * 8 + w;
    const float* Xb = X + (size_t)b * Tn * Cn;

    // my 9 normalized scores (j = q*32 + lane)
    const float* srow = g_scores + ((size_t)b * NE + i) * NO;
    const float* rnb  = g_rnormO + b * NO;
    float sc[9];
    #pragma unroll
    for (int q = 0; q < 9; q++) sc[q] = srow[q * 32 + lane] * rnb[q * 32 + lane];

    float m = sc[0];
    #pragma unroll
    for (int q = 1; q < 9; q++) m = fmaxf(m, sc[q]);
    #pragma unroll
    for (int o = 16; o > 0; o >>= 1) m = fmaxf(m, __shfl_xor_sync(0xffffffffu, m, o));
    const float thr = m - 0.012f * g_anorm[b * NE + i];

    // cache a_i in registers
    float4 a[8];
    const float* pa = Xb + (size_t)(2 * i + 2) * Cn;
    #pragma unroll
    for (int q = 0; q < 8; q++) a[q] = *(const float4*)(pa + q * 128 + lane * 4);

    float best = -3.0e38f; int bj = 0;
    #pragma unroll 1
    for (int q = 0; q < 9; q++) {                 // ascending q, ascending bit => ascending j
        unsigned mask = __ballot_sync(0xffffffffu, sc[q] >= thr);
        while (mask) {
            const int bit = __ffs(mask) - 1;
            mask &= mask - 1;
            const int j = q * 32 + bit;
            const float v = exact_score(a, Xb + (size_t)(2 * j + 1) * Cn, lane, rnb[j]);
            if (v > best) { best = v; bj = j; }   // strict '>' keeps lowest j on tie
        }
    }
    if (lane == 0) g_dst[b * NE + i] = bj;
}

// ---------------- K3: deterministic CSR build (parallel prefix, no atomics) ----------------
__global__ __launch_bounds__(288) void k_build_csr() {
    __shared__ int s_dst[NE];
    __shared__ int s_ws[9];
    const int b = blockIdx.x, t = threadIdx.x, wid = t >> 5, lane = t & 31;
    s_dst[t] = g_dst[b * NE + t];
    __syncthreads();

    int c = 0;
    #pragma unroll 4
    for (int i = 0; i < NE; i++) c += (s_dst[i] == t);

    // warp inclusive scan + cross-warp offsets
    int inc = c;
    #pragma unroll
    for (int o = 1; o < 32; o <<= 1) {
        const int v = __shfl_up_sync(0xffffffffu, inc, o);
        if (lane >= o) inc += v;
    }
    if (lane == 31) s_ws[wid] = inc;
    __syncthreads();
    int wo = 0;
    #pragma unroll
    for (int wv = 0; wv < 9; wv++) wo += (wv < wid) ? s_ws[wv] : 0;
    const int off = wo + inc - c;   // exclusive prefix

    int wv = 0;
    for (int i = 0; i < NE; i++)
        if (s_dst[i] == t) g_list[b * NE + off + (wv++)] = i;   // ascending i
    g_off[b * NO + t] = off;
    g_cnt[b * NO + t] = c;
}

// ---------------- K4: merge via CSR gather ----------------
__global__ __launch_bounds__(256) void k_merge(const float* __restrict__ X, float* __restrict__ out) {
    const int b = blockIdx.y, row = blockIdx.x, t = threadIdx.x;
    float* orow = out + ((size_t)b * TOUT + row) * Cn;
    const float* Xb = X + (size_t)b * Tn * Cn;

    if (row == 0) {   // lone unm token = original token 0
        *(float4*)(orow + t * 4) = *(const float4*)(Xb + t * 4);
        return;
    }
    const int j = row - 1;
    const int off = g_off[b * NO + j];
    const int cnt = g_cnt[b * NO + j];
    float4 a = *(const float4*)(Xb + (size_t)(2 * j + 1) * Cn + t * 4);
    for (int s = 0; s < cnt; s++) {
        const int i = g_list[b * NE + off + s];               // ascending i -> fixed fp order
        const float4 v = *(const float4*)(Xb + (size_t)(2 * (i + 1)) * Cn + t * 4);
        a.x += v.x; a.y += v.y; a.z += v.z; a.w += v.w;
    }
    const float inv = 1.0f / (float)(cnt + 1);
    a.x *= inv; a.y *= inv; a.z *= inv; a.w *= inv;
    *(float4*)(orow + t * 4) = a;
}

// ---------------- launch ----------------
extern "C" void kernel_launch(void* const* d_in, const int* in_sizes, int n_in,
                              void* d_out, int out_size) {
    const float* X = (const float*)d_in[0];
    float* out = (float*)d_out;

    k_gemm        <<<dim3(3, 3, Bn), 256>>>(X);
    k_filter_exact<<<Bn * 36, 256>>>(X);
    k_build_csr   <<<Bn, 288>>>();
    k_merge       <<<dim3(TOUT, Bn), 256>>>(X, out);
}